// round 13
// baseline (speedup 1.0000x reference)
#include <cuda_runtime.h>
#include <cuda_bf16.h>
#include <cstdint>

#define N_ROWS 8192
#define K_CENT 4096
#define D_DIM  256
#define LOG2E  1.4426950408889634f

#define BM 128
#define BN 128
#define NCH_TOTAL ((N_ROWS / BM) * (K_CENT / BN))   // 2048 chunks total
#define KSEG_PER_M (K_CENT / BN)                    // 32 k-segments per m-block
#define NTHREADS 512                                // 16 warps, 4x4 grid, 32x32/warp

// Row stride in smem: 512B data + 16B pad -> conflict-free ldmatrix
#define RSTRIDE 528

// ---------------- smem layout (bytes) ----------------
#define SM_WEXP  0                       // 2 x 512B (float[128] per chunk)
#define SM_RED   1024                    // 4 x 128 floats = 2048B
#define SM_X     3072                    // 128 rows x 528B = 67584
#define SM_B0    (SM_X + 128 * RSTRIDE)
#define SM_B1    (SM_B0 + 128 * RSTRIDE)
#define SMEM_TOTAL (SM_B1 + 128 * RSTRIDE)   // 205824 bytes

// ---------------- device scratch (no allocs allowed) ----------------
__device__ __align__(16) __nv_bfloat16 g_xb[N_ROWS * D_DIM];
__device__ __align__(16) __nv_bfloat16 g_cb[K_CENT * D_DIM];
__device__ __align__(16) float    g_ax[N_ROWS];       // -sigma*log2e*|x|^2
__device__ __align__(16) float    g_wexp[K_CENT];     // w * 2^(-sigma*log2e*|c|^2)
__device__ __align__(16) float    g_part[KSEG_PER_M][N_ROWS];
__device__            unsigned    g_cnt[N_ROWS / BM]; // per-m arrival counters

// ---------------- PTX helpers (sm_103-baseline only!) ----------------
static __device__ __forceinline__ uint32_t smem_u32(const void* p) {
    uint32_t a;
    asm("{ .reg .u64 t; cvta.to.shared.u64 t, %1; cvt.u32.u64 %0, t; }"
        : "=r"(a) : "l"(p));
    return a;
}

#define CPA16(dst, src) \
    asm volatile("cp.async.cg.shared.global [%0], [%1], 16;" \
                 :: "r"((uint32_t)(dst)), "l"(src) : "memory")
#define CPA_COMMIT() asm volatile("cp.async.commit_group;" ::: "memory")
#define CPA_WAIT0()  asm volatile("cp.async.wait_group 0;" ::: "memory")

#define LDMATRIX_X4(r0, r1, r2, r3, addr) \
    asm volatile("ldmatrix.sync.aligned.m8n8.x4.shared.b16 {%0,%1,%2,%3}, [%4];" \
                 : "=r"(r0), "=r"(r1), "=r"(r2), "=r"(r3) : "r"(addr))

#define MMA_BF16(d, a0, a1, a2, a3, b0, b1)                                   \
    asm volatile(                                                             \
        "mma.sync.aligned.m16n8k16.row.col.f32.bf16.bf16.f32 "                \
        "{%0,%1,%2,%3}, {%4,%5,%6,%7}, {%8,%9}, {%10,%11,%12,%13};"           \
        : "=f"((d)[0]), "=f"((d)[1]), "=f"((d)[2]), "=f"((d)[3])              \
        : "r"(a0), "r"(a1), "r"(a2), "r"(a3), "r"(b0), "r"(b1),               \
          "f"((d)[0]), "f"((d)[1]), "f"((d)[2]), "f"((d)[3]))

static __device__ __forceinline__ float ex2f(float a) {
    float p;
    asm("ex2.approx.ftz.f32 %0, %1;" : "=f"(p) : "f"(a));
    return p;
}

// ---------------- fused prep kernel ----------------
__global__ void __launch_bounds__(256)
prep_kernel(const float* __restrict__ x, const float* __restrict__ c,
            const float* __restrict__ w, const float* __restrict__ sigma) {
    int row  = blockIdx.x * 8 + (threadIdx.x >> 5);
    int lane = threadIdx.x & 31;
    const bool is_x = row < N_ROWS;
    int r = is_x ? row : row - N_ROWS;
    const float* src_f = is_x ? (x + (size_t)r * D_DIM) : (c + (size_t)r * D_DIM);
    __nv_bfloat16* dst = is_x ? (g_xb + (size_t)r * D_DIM) : (g_cb + (size_t)r * D_DIM);

    const float4* src = reinterpret_cast<const float4*>(src_f);
    float4 v0 = src[lane], v1 = src[lane + 32];
    __nv_bfloat162* o2 = reinterpret_cast<__nv_bfloat162*>(dst);
    o2[lane * 2 + 0]        = __floats2bfloat162_rn(v0.x, v0.y);
    o2[lane * 2 + 1]        = __floats2bfloat162_rn(v0.z, v0.w);
    o2[(lane + 32) * 2 + 0] = __floats2bfloat162_rn(v1.x, v1.y);
    o2[(lane + 32) * 2 + 1] = __floats2bfloat162_rn(v1.z, v1.w);
    float s = v0.x * v0.x + v0.y * v0.y + v0.z * v0.z + v0.w * v0.w
            + v1.x * v1.x + v1.y * v1.y + v1.z * v1.z + v1.w * v1.w;
#pragma unroll
    for (int o = 16; o > 0; o >>= 1) s += __shfl_xor_sync(0xffffffffu, s, o);
    if (lane == 0) {
        float a = -LOG2E * sigma[0] * s;
        if (is_x) g_ax[r] = a;
        else      g_wexp[r] = w[r] * ex2f(a);
    }
}

// one epilogue cell: acc[mt][nt], wexp base wv; rowacc index mt*2+{0,1}
#define EPI_CELL(A, mt, nt, wv)                                               \
    do {                                                                      \
        float2 we = *reinterpret_cast<const float2*>(                         \
            (wv) + wn * 32 + (nt) * 8 + 2 * (lane & 3));                      \
        float p0 = ex2f((A)[mt][nt][0] * S2);                                 \
        float p1 = ex2f((A)[mt][nt][1] * S2);                                 \
        float p2 = ex2f((A)[mt][nt][2] * S2);                                 \
        float p3 = ex2f((A)[mt][nt][3] * S2);                                 \
        rowacc[(mt) * 2 + 0] = fmaf(p0, we.x, rowacc[(mt) * 2 + 0]);          \
        rowacc[(mt) * 2 + 0] = fmaf(p1, we.y, rowacc[(mt) * 2 + 0]);          \
        rowacc[(mt) * 2 + 1] = fmaf(p2, we.x, rowacc[(mt) * 2 + 1]);          \
        rowacc[(mt) * 2 + 1] = fmaf(p3, we.y, rowacc[(mt) * 2 + 1]);          \
    } while (0)

// ---------------- persistent main HMMA kernel: 16 warps, 32x32/warp --------
__global__ void __launch_bounds__(NTHREADS, 1)
rbf_main_kernel(const float* __restrict__ sigma, float* __restrict__ out) {
    extern __shared__ char smem[];
    const uint32_t sb = smem_u32(smem);
    const int tid  = threadIdx.x;
    const int lane = tid & 31;
    const int wid  = tid >> 5;
    const int wm   = wid >> 2;     // 0..3  (32-row slab)
    const int wn   = wid & 3;      // 0..3  (32-col slab)

    const int G  = gridDim.x;
    const int t0 = (int)(((long long)blockIdx.x * NCH_TOTAL) / G);
    const int t1 = (int)(((long long)(blockIdx.x + 1) * NCH_TOTAL) / G);
    if (t0 >= t1) return;

    const float S2 = 2.0f * LOG2E * sigma[0];

    // per-lane ldmatrix address pieces
    const int a_row = (lane & 7) + 8 * ((lane >> 3) & 1);
    const int a_kb  = (lane >> 4) * 16;
    uint32_t addrA[2];
#pragma unroll
    for (int mt = 0; mt < 2; mt++)
        addrA[mt] = sb + SM_X + (wm * 32 + mt * 16 + a_row) * RSTRIDE + a_kb;
    // B pair-load line: one x4 covers an (nt-even, nt-odd) pair for one k16
    const uint32_t bline2 =
        (uint32_t)(wn * 32 + ((lane >> 4) & 1) * 8 + (lane & 7)) * RSTRIDE
        + ((lane >> 3) & 1) * 16;

    float* red = reinterpret_cast<float*>(smem + SM_RED);
    __shared__ unsigned s_prev;

    int c = t0;
    while (c < t1) {
        const int m    = c >> 5;
        const int rend = min(t1, (m + 1) << 5);
        const int m0   = m * BM;
        const int ka   = c & 31;

        // ---- run prologue: X(m) + B(chunk c) + wexp(c) ----
        {
            const char* xg = (const char*)g_xb + (size_t)m0 * D_DIM * 2;
            const char* bg = (const char*)g_cb + (size_t)(c & 31) * BN * D_DIM * 2;
            const uint32_t bdst = sb + ((c & 1) ? SM_B1 : SM_B0);
#pragma unroll
            for (int j = 0; j < 8; j++) {
                int i = tid + j * NTHREADS;
                int row = i >> 5, c16 = i & 31;
                CPA16(sb + SM_X + row * RSTRIDE + c16 * 16, xg + (size_t)i * 16);
                CPA16(bdst     + row * RSTRIDE + c16 * 16, bg + (size_t)i * 16);
            }
            if (tid < 32)
                CPA16(sb + SM_WEXP + (c & 1) * 512 + tid * 16,
                      (const char*)(g_wexp + (size_t)(c & 31) * BN) + tid * 16);
            CPA_COMMIT();
        }

        // prefetch per-row 2^ax while the cp.async drains
        float axe[4];
#pragma unroll
        for (int r = 0; r < 4; r++)
            axe[r] = ex2f(g_ax[m0 + wm * 32 + (r >> 1) * 16 + (r & 1) * 8 + (lane >> 2)]);
        float rowacc[4];
#pragma unroll
        for (int r = 0; r < 4; r++) rowacc[r] = 0.0f;

        CPA_WAIT0();
        __syncthreads();

        // ---- chunk loop over this run's k-segments ----
        for (int cc = c; cc < rend; cc++) {
            // 1. prefetch next chunk of the run
            if (cc + 1 < rend) {
                const int ks1 = (cc + 1) & 31;
                const char* bg = (const char*)g_cb + (size_t)ks1 * BN * D_DIM * 2;
                const uint32_t bdst = sb + (((cc + 1) & 1) ? SM_B1 : SM_B0);
#pragma unroll
                for (int j = 0; j < 8; j++) {
                    int i = tid + j * NTHREADS;
                    int row = i >> 5, c16 = i & 31;
                    CPA16(bdst + row * RSTRIDE + c16 * 16, bg + (size_t)i * 16);
                }
                if (tid < 32)
                    CPA16(sb + SM_WEXP + ((cc + 1) & 1) * 512 + tid * 16,
                          (const char*)(g_wexp + (size_t)ks1 * BN) + tid * 16);
                CPA_COMMIT();
            }

            const uint32_t bbase = sb + ((cc & 1) ? SM_B1 : SM_B0) + bline2;
            const float* wv = reinterpret_cast<const float*>(
                smem + SM_WEXP + (cc & 1) * 512);

            // 2. GEMM chunk cc: 32x32 per warp, 8 independent accumulators
            float acc[2][4][4];
#pragma unroll
            for (int mt = 0; mt < 2; mt++)
#pragma unroll
                for (int nt = 0; nt < 4; nt++)
#pragma unroll
                    for (int e = 0; e < 4; e++) acc[mt][nt][e] = 0.0f;
#pragma unroll
            for (int ks = 0; ks < 16; ks++) {
                uint32_t a[2][4];
#pragma unroll
                for (int mt = 0; mt < 2; mt++)
                    LDMATRIX_X4(a[mt][0], a[mt][1], a[mt][2], a[mt][3],
                                addrA[mt] + ks * 32);
                uint32_t e0, e1, o0, o1, e2, e3, o2, o3;
                LDMATRIX_X4(e0, e1, o0, o1, bbase + ks * 32);
                LDMATRIX_X4(e2, e3, o2, o3, bbase + 16 * RSTRIDE + ks * 32);
#pragma unroll
                for (int mt = 0; mt < 2; mt++) {
                    MMA_BF16(acc[mt][0], a[mt][0], a[mt][1], a[mt][2], a[mt][3], e0, e1);
                    MMA_BF16(acc[mt][1], a[mt][0], a[mt][1], a[mt][2], a[mt][3], o0, o1);
                    MMA_BF16(acc[mt][2], a[mt][0], a[mt][1], a[mt][2], a[mt][3], e2, e3);
                    MMA_BF16(acc[mt][3], a[mt][0], a[mt][1], a[mt][2], a[mt][3], o2, o3);
                }
            }

            // 3. epilogue (8 cells; hidden by peer warps' MMA issue)
#pragma unroll
            for (int mt = 0; mt < 2; mt++) {
                EPI_CELL(acc, mt, 0, wv);
                EPI_CELL(acc, mt, 1, wv);
                EPI_CELL(acc, mt, 2, wv);
                EPI_CELL(acc, mt, 3, wv);
            }

            // 4. next buffer resident + all warps done with current buffers
            CPA_WAIT0();
            __syncthreads();
        }

        // ---- run flush: apply 2^ax per row, reduce, publish partial ----
#pragma unroll
        for (int r = 0; r < 4; r++) {
            rowacc[r] *= axe[r];
            rowacc[r] += __shfl_xor_sync(0xffffffffu, rowacc[r], 1);
            rowacc[r] += __shfl_xor_sync(0xffffffffu, rowacc[r], 2);
        }
        if ((lane & 3) == 0) {
#pragma unroll
            for (int r = 0; r < 4; r++) {
                int row = wm * 32 + (r >> 1) * 16 + (r & 1) * 8 + (lane >> 2);
                red[wn * 128 + row] = rowacc[r];
            }
        }
        __syncthreads();

        const int nseg = rend - c;
        if (tid < 128) {
            float s = red[tid] + red[128 + tid] + red[256 + tid] + red[384 + tid];
            g_part[ka][m0 + tid] = s;
            for (int sl = ka + 1; sl < ka + nseg; sl++)
                g_part[sl][m0 + tid] = 0.0f;
        }
        __threadfence();
        __syncthreads();
        if (tid == 0) s_prev = atomicAdd(&g_cnt[m], (unsigned)nseg);
        __syncthreads();
        if (s_prev + (unsigned)nseg == (unsigned)KSEG_PER_M) {
            __threadfence();
            if (tid < 128) {
                float o = 0.0f;
#pragma unroll
                for (int sl = 0; sl < KSEG_PER_M; sl++)
                    o += g_part[sl][m0 + tid];
                out[m0 + tid] = o;
            }
            if (tid == 0) g_cnt[m] = 0;   // restore for next graph replay
        }
        // next run's prologue syncs before any smem reuse

        c = rend;
    }
}

// ---------------- launch ----------------
extern "C" void kernel_launch(void* const* d_in, const int* in_sizes, int n_in,
                              void* d_out, int out_size) {
    const float* x  = (const float*)d_in[0];
    const float* c  = (const float*)d_in[1];
    const float* w  = (const float*)d_in[2];
    const float* sg = (const float*)d_in[3];

    int nsm = 0;
    cudaDeviceGetAttribute(&nsm, cudaDevAttrMultiProcessorCount, 0);
    if (nsm <= 0) nsm = 148;            // safe fallback
    if (nsm > NCH_TOTAL) nsm = NCH_TOTAL;

    cudaFuncSetAttribute(rbf_main_kernel,
                         cudaFuncAttributeMaxDynamicSharedMemorySize, SMEM_TOTAL);

    prep_kernel<<<(N_ROWS + K_CENT) / 8, 256>>>(x, c, w, sg);
    rbf_main_kernel<<<nsm, NTHREADS, SMEM_TOTAL>>>(sg, (float*)d_out);
}

// round 14
// speedup vs baseline: 1.0043x; 1.0043x over previous
#include <cuda_runtime.h>
#include <cuda_bf16.h>
#include <cstdint>

#define N_ROWS 8192
#define K_CENT 4096
#define D_DIM  256
#define LOG2E  1.4426950408889634f

#define BM 128
#define BN 64
#define NU_TOTAL ((N_ROWS / BM) * (K_CENT / BN))    // 8192 ... (64 m * 64 k) = 4096 units
#define KSEG_PER_M (K_CENT / BN)                    // 64 k-units per m-block
#define NTHREADS 256                                // 8 warps, 4x2 grid, 32x32/warp
#define NSLOT 5                                     // max covering CTAs per m (<=4) + margin

// Row stride in smem: 512B data + 16B pad -> conflict-free ldmatrix
#define RSTRIDE 528

// ---------------- smem layout (bytes) ----------------
#define SM_WEXP  0                       // 2 x 256B (float[64] per unit)
#define SM_RED   512                     // 2 x 128 floats = 1024B
#define SM_X0    1536                    // 128 rows x 528B = 67584
#define SM_X1    (SM_X0 + 128 * RSTRIDE)
#define SM_B0    (SM_X1 + 128 * RSTRIDE)
#define SM_B1    (SM_B0 + 64 * RSTRIDE)
#define SMEM_TOTAL (SM_B1 + 64 * RSTRIDE)   // 204288 bytes

// ---------------- device scratch (no allocs allowed) ----------------
__device__ __align__(16) __nv_bfloat16 g_xb[N_ROWS * D_DIM];
__device__ __align__(16) __nv_bfloat16 g_cb[K_CENT * D_DIM];
__device__ __align__(16) float    g_ax[N_ROWS];       // -sigma*log2e*|x|^2
__device__ __align__(16) float    g_wexp[K_CENT];     // w * 2^(-sigma*log2e*|c|^2)
__device__ __align__(16) float    g_part[NSLOT][N_ROWS];
__device__            unsigned    g_cnt[N_ROWS / BM]; // per-m arrival counters

// ---------------- PTX helpers (sm_103-baseline only!) ----------------
static __device__ __forceinline__ uint32_t smem_u32(const void* p) {
    uint32_t a;
    asm("{ .reg .u64 t; cvta.to.shared.u64 t, %1; cvt.u32.u64 %0, t; }"
        : "=r"(a) : "l"(p));
    return a;
}

#define CPA16(dst, src) \
    asm volatile("cp.async.cg.shared.global [%0], [%1], 16;" \
                 :: "r"((uint32_t)(dst)), "l"(src) : "memory")
#define CPA_COMMIT() asm volatile("cp.async.commit_group;" ::: "memory")
#define CPA_WAIT0()  asm volatile("cp.async.wait_group 0;" ::: "memory")

#define LDMATRIX_X4(r0, r1, r2, r3, addr) \
    asm volatile("ldmatrix.sync.aligned.m8n8.x4.shared.b16 {%0,%1,%2,%3}, [%4];" \
                 : "=r"(r0), "=r"(r1), "=r"(r2), "=r"(r3) : "r"(addr))

#define MMA_BF16(d, a0, a1, a2, a3, b0, b1)                                   \
    asm volatile(                                                             \
        "mma.sync.aligned.m16n8k16.row.col.f32.bf16.bf16.f32 "                \
        "{%0,%1,%2,%3}, {%4,%5,%6,%7}, {%8,%9}, {%10,%11,%12,%13};"           \
        : "=f"((d)[0]), "=f"((d)[1]), "=f"((d)[2]), "=f"((d)[3])              \
        : "r"(a0), "r"(a1), "r"(a2), "r"(a3), "r"(b0), "r"(b1),               \
          "f"((d)[0]), "f"((d)[1]), "f"((d)[2]), "f"((d)[3]))

static __device__ __forceinline__ float ex2f(float a) {
    float p;
    asm("ex2.approx.ftz.f32 %0, %1;" : "=f"(p) : "f"(a));
    return p;
}

// ---------------- fused prep kernel ----------------
__global__ void __launch_bounds__(256)
prep_kernel(const float* __restrict__ x, const float* __restrict__ c,
            const float* __restrict__ w, const float* __restrict__ sigma) {
    int row  = blockIdx.x * 8 + (threadIdx.x >> 5);
    int lane = threadIdx.x & 31;
    const bool is_x = row < N_ROWS;
    int r = is_x ? row : row - N_ROWS;
    const float* src_f = is_x ? (x + (size_t)r * D_DIM) : (c + (size_t)r * D_DIM);
    __nv_bfloat16* dst = is_x ? (g_xb + (size_t)r * D_DIM) : (g_cb + (size_t)r * D_DIM);

    const float4* src = reinterpret_cast<const float4*>(src_f);
    float4 v0 = src[lane], v1 = src[lane + 32];
    __nv_bfloat162* o2 = reinterpret_cast<__nv_bfloat162*>(dst);
    o2[lane * 2 + 0]        = __floats2bfloat162_rn(v0.x, v0.y);
    o2[lane * 2 + 1]        = __floats2bfloat162_rn(v0.z, v0.w);
    o2[(lane + 32) * 2 + 0] = __floats2bfloat162_rn(v1.x, v1.y);
    o2[(lane + 32) * 2 + 1] = __floats2bfloat162_rn(v1.z, v1.w);
    float s = v0.x * v0.x + v0.y * v0.y + v0.z * v0.z + v0.w * v0.w
            + v1.x * v1.x + v1.y * v1.y + v1.z * v1.z + v1.w * v1.w;
#pragma unroll
    for (int o = 16; o > 0; o >>= 1) s += __shfl_xor_sync(0xffffffffu, s, o);
    if (lane == 0) {
        float a = -LOG2E * sigma[0] * s;
        if (is_x) g_ax[r] = a;
        else      g_wexp[r] = w[r] * ex2f(a);
    }
}

// one epilogue cell: A[nt][4] accumulator block, global row-pair mtabs (0|1),
// n-tile nt (0..3 within the warp's 32 cols), wexp base wv
#define EPI_CELL(A, mtabs, nt, wv)                                            \
    do {                                                                      \
        float2 we = *reinterpret_cast<const float2*>(                         \
            (wv) + wn * 32 + (nt) * 8 + 2 * (lane & 3));                      \
        float p0 = ex2f((A)[nt][0] * S2);                                     \
        float p1 = ex2f((A)[nt][1] * S2);                                     \
        float p2 = ex2f((A)[nt][2] * S2);                                     \
        float p3 = ex2f((A)[nt][3] * S2);                                     \
        rowacc[(mtabs) * 2 + 0] = fmaf(p0, we.x, rowacc[(mtabs) * 2 + 0]);    \
        rowacc[(mtabs) * 2 + 0] = fmaf(p1, we.y, rowacc[(mtabs) * 2 + 0]);    \
        rowacc[(mtabs) * 2 + 1] = fmaf(p2, we.x, rowacc[(mtabs) * 2 + 1]);    \
        rowacc[(mtabs) * 2 + 1] = fmaf(p3, we.y, rowacc[(mtabs) * 2 + 1]);    \
    } while (0)

// ---------------- persistent main HMMA kernel ----------------
__global__ void __launch_bounds__(NTHREADS, 1)
rbf_main_kernel(const float* __restrict__ sigma, float* __restrict__ out) {
    extern __shared__ char smem[];
    const uint32_t sb = smem_u32(smem);
    const int tid  = threadIdx.x;
    const int lane = tid & 31;
    const int wid  = tid >> 5;
    const int wm   = wid >> 1;     // 0..3  (32-row slab)
    const int wn   = wid & 1;      // 0..1  (32-col slab)

    const int G  = gridDim.x;
    const int b  = blockIdx.x;
    const int t0 = (int)(((long long)b * NU_TOTAL) / G);
    const int t1 = (int)(((long long)(b + 1) * NU_TOTAL) / G);
    if (t0 >= t1) return;

    const float S2 = 2.0f * LOG2E * sigma[0];

    // per-lane ldmatrix address pieces (buffer-relative, computed per run)
    const int a_row = (lane & 7) + 8 * ((lane >> 3) & 1);
    const int a_kb  = (lane >> 4) * 16;
    const uint32_t a_off0 = (uint32_t)(wm * 32 + 0 * 16 + a_row) * RSTRIDE + a_kb;
    const uint32_t a_off1 = (uint32_t)(wm * 32 + 1 * 16 + a_row) * RSTRIDE + a_kb;
    // B pair-load line: one x4 covers (nt-even, nt-odd) for one k16
    const uint32_t bline2 =
        (uint32_t)(wn * 32 + ((lane >> 4) & 1) * 8 + (lane & 7)) * RSTRIDE
        + ((lane >> 3) & 1) * 16;

    float* red = reinterpret_cast<float*>(smem + SM_RED);
    __shared__ unsigned s_prev;

    int c = t0;
    int xbuf = 0;
    bool first = true;

    while (c < t1) {
        const int m    = c >> 6;
        const int rend = min(t1, (m + 1) << 6);
        const int m0   = m * BM;

        const uint32_t xbase = sb + (xbuf ? SM_X1 : SM_X0);
        const uint32_t addrA0 = xbase + a_off0;
        const uint32_t addrA1 = xbase + a_off1;

        if (first) {
            // ---- first-run prologue: X(m) + B(unit c) + wexp(c) ----
            const char* xg = (const char*)g_xb + (size_t)m0 * D_DIM * 2;
            const char* bg = (const char*)g_cb + (size_t)(c & 63) * BN * D_DIM * 2;
            const uint32_t bdst = sb + ((c & 1) ? SM_B1 : SM_B0);
#pragma unroll
            for (int j = 0; j < 16; j++) {
                int i = tid + j * NTHREADS;
                int row = i >> 5, c16 = i & 31;
                CPA16(xbase + row * RSTRIDE + c16 * 16, xg + (size_t)i * 16);
                if (j < 8)
                    CPA16(bdst + row * RSTRIDE + c16 * 16, bg + (size_t)i * 16);
            }
            if (tid < 16)
                CPA16(sb + SM_WEXP + (c & 1) * 256 + tid * 16,
                      (const char*)(g_wexp + (size_t)(c & 63) * BN) + tid * 16);
            CPA_COMMIT();
        }

        // per-row 2^ax (used only at flush; latency has slack)
        float axe[4];
#pragma unroll
        for (int r = 0; r < 4; r++)
            axe[r] = ex2f(g_ax[m0 + wm * 32 + (r >> 1) * 16 + (r & 1) * 8 + (lane >> 2)]);
        float rowacc[4];
#pragma unroll
        for (int r = 0; r < 4; r++) rowacc[r] = 0.0f;

        if (first) {
            CPA_WAIT0();
            __syncthreads();
            first = false;
        }
        // subsequent runs: X/B/wexp already resident (prefetched + synced below)

        // ---- unit loop over this run's k-units ----
        for (int cc = c; cc < rend; cc++) {
            // 1. prefetch next unit (B+wexp); at run crossing also next X
            const int nx = cc + 1;
            if (nx < rend) {
                const char* bg = (const char*)g_cb + (size_t)(nx & 63) * BN * D_DIM * 2;
                const uint32_t bdst = sb + ((nx & 1) ? SM_B1 : SM_B0);
#pragma unroll
                for (int j = 0; j < 8; j++) {
                    int i = tid + j * NTHREADS;
                    int row = i >> 5, c16 = i & 31;
                    CPA16(bdst + row * RSTRIDE + c16 * 16, bg + (size_t)i * 16);
                }
                if (tid < 16)
                    CPA16(sb + SM_WEXP + (nx & 1) * 256 + tid * 16,
                          (const char*)(g_wexp + (size_t)(nx & 63) * BN) + tid * 16);
            } else if (nx < t1) {
                // run crossing: prefetch next run's X + first B + wexp
                const int m1 = nx >> 6;
                const char* xg = (const char*)g_xb + (size_t)m1 * BM * D_DIM * 2;
                const char* bg = (const char*)g_cb + (size_t)(nx & 63) * BN * D_DIM * 2;
                const uint32_t xdst = sb + (xbuf ? SM_X0 : SM_X1);
                const uint32_t bdst = sb + ((nx & 1) ? SM_B1 : SM_B0);
#pragma unroll
                for (int j = 0; j < 16; j++) {
                    int i = tid + j * NTHREADS;
                    int row = i >> 5, c16 = i & 31;
                    CPA16(xdst + row * RSTRIDE + c16 * 16, xg + (size_t)i * 16);
                    if (j < 8)
                        CPA16(bdst + row * RSTRIDE + c16 * 16, bg + (size_t)i * 16);
                }
                if (tid < 16)
                    CPA16(sb + SM_WEXP + (nx & 1) * 256 + tid * 16,
                          (const char*)(g_wexp + (size_t)(nx & 63) * BN) + tid * 16);
            }
            CPA_COMMIT();

            const uint32_t bbase = sb + ((cc & 1) ? SM_B1 : SM_B0) + bline2;
            const float* wv = reinterpret_cast<const float*>(
                smem + SM_WEXP + (cc & 1) * 256);

            // 2a. group 0: m-tile 0 (rows wm*32 .. +15)
            float acc0[4][4];
#pragma unroll
            for (int nt = 0; nt < 4; nt++)
#pragma unroll
                for (int e = 0; e < 4; e++) acc0[nt][e] = 0.0f;
#pragma unroll
            for (int ks = 0; ks < 16; ks++) {
                uint32_t a0, a1, a2, a3;
                LDMATRIX_X4(a0, a1, a2, a3, addrA0 + ks * 32);
                uint32_t e0, e1, o0, o1, e2, e3, o2, o3;
                LDMATRIX_X4(e0, e1, o0, o1, bbase + ks * 32);
                LDMATRIX_X4(e2, e3, o2, o3, bbase + 16 * RSTRIDE + ks * 32);
                MMA_BF16(acc0[0], a0, a1, a2, a3, e0, e1);
                MMA_BF16(acc0[1], a0, a1, a2, a3, o0, o1);
                MMA_BF16(acc0[2], a0, a1, a2, a3, e2, e3);
                MMA_BF16(acc0[3], a0, a1, a2, a3, o2, o3);
            }

            // 2b. group 1: m-tile 1 + interleaved epilogue of group 0
            float acc1[4][4];
#pragma unroll
            for (int nt = 0; nt < 4; nt++)
#pragma unroll
                for (int e = 0; e < 4; e++) acc1[nt][e] = 0.0f;
#pragma unroll
            for (int ks = 0; ks < 16; ks++) {
                uint32_t a0, a1, a2, a3;
                LDMATRIX_X4(a0, a1, a2, a3, addrA1 + ks * 32);
                uint32_t e0, e1, o0, o1, e2, e3, o2, o3;
                LDMATRIX_X4(e0, e1, o0, o1, bbase + ks * 32);
                LDMATRIX_X4(e2, e3, o2, o3, bbase + 16 * RSTRIDE + ks * 32);
                MMA_BF16(acc1[0], a0, a1, a2, a3, e0, e1);
                MMA_BF16(acc1[1], a0, a1, a2, a3, o0, o1);
                MMA_BF16(acc1[2], a0, a1, a2, a3, e2, e3);
                MMA_BF16(acc1[3], a0, a1, a2, a3, o2, o3);
                if ((ks & 3) == 1)
                    EPI_CELL(acc0, 0, (ks >> 2), wv);
            }
            // tail: group-1 cells
            EPI_CELL(acc1, 1, 0, wv);
            EPI_CELL(acc1, 1, 1, wv);
            EPI_CELL(acc1, 1, 2, wv);
            EPI_CELL(acc1, 1, 3, wv);

            // 3. buffers for next unit resident + all warps done with current
            CPA_WAIT0();
            __syncthreads();
        }

        // ---- run flush: apply 2^ax, reduce, publish partial ----
#pragma unroll
        for (int r = 0; r < 4; r++) {
            rowacc[r] *= axe[r];
            rowacc[r] += __shfl_xor_sync(0xffffffffu, rowacc[r], 1);
            rowacc[r] += __shfl_xor_sync(0xffffffffu, rowacc[r], 2);
        }
        if ((lane & 3) == 0) {
#pragma unroll
            for (int r = 0; r < 4; r++) {
                int row = wm * 32 + (r >> 1) * 16 + (r & 1) * 8 + (lane >> 2);
                red[wn * 128 + row] = rowacc[r];
            }
        }
        __syncthreads();

        // covering-CTA walk: slot = b - b_first, nslots = b_last - b_first + 1
        const long long mm0 = (long long)m << 6;
        const long long mm1 = mm0 + 64;
        int bf = b;
        while (bf > 0 && ((long long)bf * NU_TOTAL) / G > mm0) bf--;
        int bl = b;
        while (bl + 1 < G && (((long long)(bl + 1) * NU_TOTAL) / G) < mm1) bl++;
        const int slot = b - bf;
        const int nsl  = bl - bf + 1;

        const int nseg = rend - c;
        if (tid < 128)
            g_part[slot][m0 + tid] = red[tid] + red[128 + tid];
        __threadfence();
        __syncthreads();
        if (tid == 0) s_prev = atomicAdd(&g_cnt[m], (unsigned)nseg);
        __syncthreads();
        if (s_prev + (unsigned)nseg == (unsigned)KSEG_PER_M) {
            __threadfence();
            if (tid < 128) {
                float o = 0.0f;
                for (int sl = 0; sl < nsl; sl++)
                    o += g_part[sl][m0 + tid];
                out[m0 + tid] = o;
            }
            if (tid == 0) g_cnt[m] = 0;   // restore for next graph replay
        }

        c = rend;
        xbuf ^= 1;   // only matters if another run follows (X prefetched there)
    }
}

// ---------------- launch ----------------
extern "C" void kernel_launch(void* const* d_in, const int* in_sizes, int n_in,
                              void* d_out, int out_size) {
    const float* x  = (const float*)d_in[0];
    const float* c  = (const float*)d_in[1];
    const float* w  = (const float*)d_in[2];
    const float* sg = (const float*)d_in[3];

    int nsm = 0;
    cudaDeviceGetAttribute(&nsm, cudaDevAttrMultiProcessorCount, 0);
    if (nsm <= 0) nsm = 148;            // safe fallback
    if (nsm > NU_TOTAL) nsm = NU_TOTAL;

    cudaFuncSetAttribute(rbf_main_kernel,
                         cudaFuncAttributeMaxDynamicSharedMemorySize, SMEM_TOTAL);

    prep_kernel<<<(N_ROWS + K_CENT) / 8, 256>>>(x, c, w, sg);
    rbf_main_kernel<<<nsm, NTHREADS, SMEM_TOTAL>>>(sg, (float*)d_out);
}

// round 15
// speedup vs baseline: 1.0113x; 1.0070x over previous
#include <cuda_runtime.h>
#include <cuda_bf16.h>
#include <cstdint>

#define N_ROWS 8192
#define K_CENT 4096
#define D_DIM  256
#define LOG2E  1.4426950408889634f

#define BM 128
#define BN 128
#define NCH_TOTAL ((N_ROWS / BM) * (K_CENT / BN))   // 2048 chunks total
#define KSEG_PER_M (K_CENT / BN)                    // 32 k-segments per m-block
#define NTHREADS 256                                // 8 warps, 2x4 grid, 64x32/warp
#define NSLOT 5                                     // max covering CTAs per m (<=4) + margin

// Row stride in smem: 512B data + 16B pad -> conflict-free ldmatrix
#define RSTRIDE 528

// ---------------- smem layout (bytes) ----------------
#define SM_WEXP  0                       // 2 x 512B (float[128] per chunk)
#define SM_RED   1024                    // 4 x 128 floats = 2048B
#define SM_X     3072                    // 128 rows x 528B = 67584
#define SM_B0    (SM_X + 128 * RSTRIDE)
#define SM_B1    (SM_B0 + 128 * RSTRIDE)
#define SMEM_TOTAL (SM_B1 + 128 * RSTRIDE)   // 205824 bytes

// ---------------- device scratch (no allocs allowed) ----------------
__device__ __align__(16) __nv_bfloat16 g_xb[N_ROWS * D_DIM];
__device__ __align__(16) __nv_bfloat16 g_cb[K_CENT * D_DIM];
__device__ __align__(16) float    g_ax[N_ROWS];       // -sigma*log2e*|x|^2
__device__ __align__(16) float    g_wexp[K_CENT];     // w * 2^(-sigma*log2e*|c|^2)
__device__ __align__(16) float    g_part[NSLOT][N_ROWS];
__device__            unsigned    g_cnt[N_ROWS / BM]; // per-m arrival counters

// ---------------- PTX helpers (sm_103-baseline only!) ----------------
static __device__ __forceinline__ uint32_t smem_u32(const void* p) {
    uint32_t a;
    asm("{ .reg .u64 t; cvta.to.shared.u64 t, %1; cvt.u32.u64 %0, t; }"
        : "=r"(a) : "l"(p));
    return a;
}

#define CPA16(dst, src) \
    asm volatile("cp.async.cg.shared.global [%0], [%1], 16;" \
                 :: "r"((uint32_t)(dst)), "l"(src) : "memory")
#define CPA_COMMIT() asm volatile("cp.async.commit_group;" ::: "memory")
#define CPA_WAIT0()  asm volatile("cp.async.wait_group 0;" ::: "memory")

#define LDMATRIX_X4(r0, r1, r2, r3, addr) \
    asm volatile("ldmatrix.sync.aligned.m8n8.x4.shared.b16 {%0,%1,%2,%3}, [%4];" \
                 : "=r"(r0), "=r"(r1), "=r"(r2), "=r"(r3) : "r"(addr))

#define MMA_BF16(d, a0, a1, a2, a3, b0, b1)                                   \
    asm volatile(                                                             \
        "mma.sync.aligned.m16n8k16.row.col.f32.bf16.bf16.f32 "                \
        "{%0,%1,%2,%3}, {%4,%5,%6,%7}, {%8,%9}, {%10,%11,%12,%13};"           \
        : "=f"((d)[0]), "=f"((d)[1]), "=f"((d)[2]), "=f"((d)[3])              \
        : "r"(a0), "r"(a1), "r"(a2), "r"(a3), "r"(b0), "r"(b1),               \
          "f"((d)[0]), "f"((d)[1]), "f"((d)[2]), "f"((d)[3]))

static __device__ __forceinline__ float ex2f(float a) {
    float p;
    asm("ex2.approx.ftz.f32 %0, %1;" : "=f"(p) : "f"(a));
    return p;
}

// ---------------- fused prep kernel ----------------
__global__ void __launch_bounds__(256)
prep_kernel(const float* __restrict__ x, const float* __restrict__ c,
            const float* __restrict__ w, const float* __restrict__ sigma) {
    int row  = blockIdx.x * 8 + (threadIdx.x >> 5);
    int lane = threadIdx.x & 31;
    const bool is_x = row < N_ROWS;
    int r = is_x ? row : row - N_ROWS;
    const float* src_f = is_x ? (x + (size_t)r * D_DIM) : (c + (size_t)r * D_DIM);
    __nv_bfloat16* dst = is_x ? (g_xb + (size_t)r * D_DIM) : (g_cb + (size_t)r * D_DIM);

    const float4* src = reinterpret_cast<const float4*>(src_f);
    float4 v0 = src[lane], v1 = src[lane + 32];
    __nv_bfloat162* o2 = reinterpret_cast<__nv_bfloat162*>(dst);
    o2[lane * 2 + 0]        = __floats2bfloat162_rn(v0.x, v0.y);
    o2[lane * 2 + 1]        = __floats2bfloat162_rn(v0.z, v0.w);
    o2[(lane + 32) * 2 + 0] = __floats2bfloat162_rn(v1.x, v1.y);
    o2[(lane + 32) * 2 + 1] = __floats2bfloat162_rn(v1.z, v1.w);
    float s = v0.x * v0.x + v0.y * v0.y + v0.z * v0.z + v0.w * v0.w
            + v1.x * v1.x + v1.y * v1.y + v1.z * v1.z + v1.w * v1.w;
#pragma unroll
    for (int o = 16; o > 0; o >>= 1) s += __shfl_xor_sync(0xffffffffu, s, o);
    if (lane == 0) {
        float a = -LOG2E * sigma[0] * s;
        if (is_x) g_ax[r] = a;
        else      g_wexp[r] = w[r] * ex2f(a);
    }
}

// one epilogue cell: array A (local mt index mtl), global row-group mtabs,
// absolute n-tile nt, wexp base wv
#define EPI_CELL(A, mtl, mtabs, nt, wv)                                       \
    do {                                                                      \
        float2 we = *reinterpret_cast<const float2*>(                         \
            (wv) + wn * 32 + (nt) * 8 + 2 * (lane & 3));                      \
        float p0 = ex2f((A)[mtl][nt][0] * S2);                                \
        float p1 = ex2f((A)[mtl][nt][1] * S2);                                \
        float p2 = ex2f((A)[mtl][nt][2] * S2);                                \
        float p3 = ex2f((A)[mtl][nt][3] * S2);                                \
        rowacc[(mtabs) * 2 + 0] = fmaf(p0, we.x, rowacc[(mtabs) * 2 + 0]);    \
        rowacc[(mtabs) * 2 + 0] = fmaf(p1, we.y, rowacc[(mtabs) * 2 + 0]);    \
        rowacc[(mtabs) * 2 + 1] = fmaf(p2, we.x, rowacc[(mtabs) * 2 + 1]);    \
        rowacc[(mtabs) * 2 + 1] = fmaf(p3, we.y, rowacc[(mtabs) * 2 + 1]);    \
    } while (0)

// ---------------- persistent main HMMA kernel ----------------
__global__ void __launch_bounds__(NTHREADS, 1)
rbf_main_kernel(const float* __restrict__ sigma, float* __restrict__ out) {
    extern __shared__ char smem[];
    const uint32_t sb = smem_u32(smem);
    const int tid  = threadIdx.x;
    const int lane = tid & 31;
    const int wid  = tid >> 5;
    const int wm   = wid >> 2;     // 0..1  (64-row slab)
    const int wn   = wid & 3;      // 0..3  (32-col slab)

    const int G  = gridDim.x;
    const int b  = blockIdx.x;
    const int t0 = (int)(((long long)b * NCH_TOTAL) / G);
    const int t1 = (int)(((long long)(b + 1) * NCH_TOTAL) / G);
    if (t0 >= t1) return;

    const float S2 = 2.0f * LOG2E * sigma[0];

    // per-lane ldmatrix address pieces
    const int a_row = (lane & 7) + 8 * ((lane >> 3) & 1);
    const int a_kb  = (lane >> 4) * 16;
    uint32_t addrA[4];
#pragma unroll
    for (int mt = 0; mt < 4; mt++)
        addrA[mt] = sb + SM_X + (wm * 64 + mt * 16 + a_row) * RSTRIDE + a_kb;
    // B pair-load line: one x4 covers an (nt-even, nt-odd) pair for one k16
    const uint32_t bline2 =
        (uint32_t)(wn * 32 + ((lane >> 4) & 1) * 8 + (lane & 7)) * RSTRIDE
        + ((lane >> 3) & 1) * 16;

    float* red = reinterpret_cast<float*>(smem + SM_RED);
    __shared__ unsigned s_prev;

    int c = t0;
    while (c < t1) {
        const int m    = c >> 5;
        const int rend = min(t1, (m + 1) << 5);
        const int m0   = m * BM;

        // ---- run prologue: X(m) + B(chunk c) + wexp(c) ----
        {
            const char* xg = (const char*)g_xb + (size_t)m0 * D_DIM * 2;
            const char* bg = (const char*)g_cb + (size_t)(c & 31) * BN * D_DIM * 2;
            const uint32_t bdst = sb + ((c & 1) ? SM_B1 : SM_B0);
#pragma unroll
            for (int j = 0; j < 16; j++) {
                int i = tid + j * NTHREADS;
                int row = i >> 5, c16 = i & 31;
                CPA16(sb + SM_X + row * RSTRIDE + c16 * 16, xg + (size_t)i * 16);
                CPA16(bdst     + row * RSTRIDE + c16 * 16, bg + (size_t)i * 16);
            }
            if (tid < 32)
                CPA16(sb + SM_WEXP + (c & 1) * 512 + tid * 16,
                      (const char*)(g_wexp + (size_t)(c & 31) * BN) + tid * 16);
            CPA_COMMIT();
        }

        // prefetch per-row 2^ax while the cp.async drains
        float axe[8];
#pragma unroll
        for (int r = 0; r < 8; r++)
            axe[r] = ex2f(g_ax[m0 + wm * 64 + (r >> 1) * 16 + (r & 1) * 8 + (lane >> 2)]);
        float rowacc[8];
#pragma unroll
        for (int r = 0; r < 8; r++) rowacc[r] = 0.0f;

        CPA_WAIT0();
        __syncthreads();

        // ---- chunk loop over this run's k-segments ----
        for (int cc = c; cc < rend; cc++) {
            // 1. prefetch next chunk of the run
            if (cc + 1 < rend) {
                const int ks1 = (cc + 1) & 31;
                const char* bg = (const char*)g_cb + (size_t)ks1 * BN * D_DIM * 2;
                const uint32_t bdst = sb + (((cc + 1) & 1) ? SM_B1 : SM_B0);
#pragma unroll
                for (int j = 0; j < 16; j++) {
                    int i = tid + j * NTHREADS;
                    int row = i >> 5, c16 = i & 31;
                    CPA16(bdst + row * RSTRIDE + c16 * 16, bg + (size_t)i * 16);
                }
                if (tid < 32)
                    CPA16(sb + SM_WEXP + ((cc + 1) & 1) * 512 + tid * 16,
                          (const char*)(g_wexp + (size_t)ks1 * BN) + tid * 16);
                CPA_COMMIT();
            }

            const uint32_t bbase = sb + ((cc & 1) ? SM_B1 : SM_B0) + bline2;
            const float* wv = reinterpret_cast<const float*>(
                smem + SM_WEXP + (cc & 1) * 512);

            // 2a. group 0: rows mt 0,1 x all nt (A loaded once, B pair x2)
            float acc0[2][4][4];
#pragma unroll
            for (int mt = 0; mt < 2; mt++)
#pragma unroll
                for (int nt = 0; nt < 4; nt++)
#pragma unroll
                    for (int e = 0; e < 4; e++) acc0[mt][nt][e] = 0.0f;
#pragma unroll
            for (int ks = 0; ks < 16; ks++) {
                uint32_t a[2][4];
#pragma unroll
                for (int mt = 0; mt < 2; mt++)
                    LDMATRIX_X4(a[mt][0], a[mt][1], a[mt][2], a[mt][3],
                                addrA[mt] + ks * 32);
                uint32_t e0, e1, o0, o1, e2, e3, o2, o3;
                LDMATRIX_X4(e0, e1, o0, o1, bbase + ks * 32);
                LDMATRIX_X4(e2, e3, o2, o3, bbase + 16 * RSTRIDE + ks * 32);
#pragma unroll
                for (int mt = 0; mt < 2; mt++) {
                    MMA_BF16(acc0[mt][0], a[mt][0], a[mt][1], a[mt][2], a[mt][3], e0, e1);
                    MMA_BF16(acc0[mt][1], a[mt][0], a[mt][1], a[mt][2], a[mt][3], o0, o1);
                    MMA_BF16(acc0[mt][2], a[mt][0], a[mt][1], a[mt][2], a[mt][3], e2, e3);
                    MMA_BF16(acc0[mt][3], a[mt][0], a[mt][1], a[mt][2], a[mt][3], o2, o3);
                }
            }

            // 2b. group 1: rows mt 2,3 + interleaved epilogue of group 0
            float acc1[2][4][4];
#pragma unroll
            for (int mt = 0; mt < 2; mt++)
#pragma unroll
                for (int nt = 0; nt < 4; nt++)
#pragma unroll
                    for (int e = 0; e < 4; e++) acc1[mt][nt][e] = 0.0f;
#pragma unroll
            for (int ks = 0; ks < 16; ks++) {
                uint32_t a[2][4];
#pragma unroll
                for (int mt = 0; mt < 2; mt++)
                    LDMATRIX_X4(a[mt][0], a[mt][1], a[mt][2], a[mt][3],
                                addrA[2 + mt] + ks * 32);
                uint32_t e0, e1, o0, o1, e2, e3, o2, o3;
                LDMATRIX_X4(e0, e1, o0, o1, bbase + ks * 32);
                LDMATRIX_X4(e2, e3, o2, o3, bbase + 16 * RSTRIDE + ks * 32);
#pragma unroll
                for (int mt = 0; mt < 2; mt++) {
                    MMA_BF16(acc1[mt][0], a[mt][0], a[mt][1], a[mt][2], a[mt][3], e0, e1);
                    MMA_BF16(acc1[mt][1], a[mt][0], a[mt][1], a[mt][2], a[mt][3], o0, o1);
                    MMA_BF16(acc1[mt][2], a[mt][0], a[mt][1], a[mt][2], a[mt][3], e2, e3);
                    MMA_BF16(acc1[mt][3], a[mt][0], a[mt][1], a[mt][2], a[mt][3], o2, o3);
                }
                if (ks & 1)
                    EPI_CELL(acc0, (ks >> 3), (ks >> 3), ((ks >> 1) & 3), wv);
            }
            // tail epilogue: group-1 cells (rows mt 2,3)
#pragma unroll
            for (int mt = 0; mt < 2; mt++) {
                EPI_CELL(acc1, mt, 2 + mt, 0, wv);
                EPI_CELL(acc1, mt, 2 + mt, 1, wv);
                EPI_CELL(acc1, mt, 2 + mt, 2, wv);
                EPI_CELL(acc1, mt, 2 + mt, 3, wv);
            }

            // 3. next buffer resident + all warps done with current buffers
            CPA_WAIT0();
            __syncthreads();
        }

        // ---- run flush: apply 2^ax per row, reduce, publish partial ----
#pragma unroll
        for (int r = 0; r < 8; r++) {
            rowacc[r] *= axe[r];
            rowacc[r] += __shfl_xor_sync(0xffffffffu, rowacc[r], 1);
            rowacc[r] += __shfl_xor_sync(0xffffffffu, rowacc[r], 2);
        }
        if ((lane & 3) == 0) {
#pragma unroll
            for (int r = 0; r < 8; r++) {
                int row = wm * 64 + (r >> 1) * 16 + (r & 1) * 8 + (lane >> 2);
                red[wn * 128 + row] = rowacc[r];
            }
        }
        __syncthreads();

        // covering-CTA walk: slot = b - b_first, nslots = b_last - b_first + 1
        const long long mm0 = (long long)m << 5;
        const long long mm1 = mm0 + KSEG_PER_M;
        int bf = b;
        while (bf > 0 && ((long long)bf * NCH_TOTAL) / G > mm0) bf--;
        int bl = b;
        while (bl + 1 < G && (((long long)(bl + 1) * NCH_TOTAL) / G) < mm1) bl++;
        const int slot = b - bf;
        const int nsl  = bl - bf + 1;

        const int nseg = rend - c;
        if (tid < 128) {
            float s = red[tid] + red[128 + tid] + red[256 + tid] + red[384 + tid];
            g_part[slot][m0 + tid] = s;
        }
        __threadfence();
        __syncthreads();
        if (tid == 0) s_prev = atomicAdd(&g_cnt[m], (unsigned)nseg);
        __syncthreads();
        if (s_prev + (unsigned)nseg == (unsigned)KSEG_PER_M) {
            // all ksegs of this m published -> finalize over covering slots
            __threadfence();
            if (tid < 128) {
                float o = 0.0f;
                for (int sl = 0; sl < nsl; sl++)
                    o += g_part[sl][m0 + tid];
                out[m0 + tid] = o;
            }
            if (tid == 0) g_cnt[m] = 0;   // restore for next graph replay
        }
        // next run's prologue syncs before any smem reuse

        c = rend;
    }
}

// ---------------- launch ----------------
extern "C" void kernel_launch(void* const* d_in, const int* in_sizes, int n_in,
                              void* d_out, int out_size) {
    const float* x  = (const float*)d_in[0];
    const float* c  = (const float*)d_in[1];
    const float* w  = (const float*)d_in[2];
    const float* sg = (const float*)d_in[3];

    int nsm = 0;
    cudaDeviceGetAttribute(&nsm, cudaDevAttrMultiProcessorCount, 0);
    if (nsm <= 0) nsm = 148;            // safe fallback
    if (nsm > NCH_TOTAL) nsm = NCH_TOTAL;

    cudaFuncSetAttribute(rbf_main_kernel,
                         cudaFuncAttributeMaxDynamicSharedMemorySize, SMEM_TOTAL);

    prep_kernel<<<(N_ROWS + K_CENT) / 8, 256>>>(x, c, w, sg);
    rbf_main_kernel<<<nsm, NTHREADS, SMEM_TOTAL>>>(sg, (float*)d_out);
}

// round 16
// speedup vs baseline: 1.0398x; 1.0282x over previous
#include <cuda_runtime.h>
#include <cuda_bf16.h>
#include <cstdint>

#define N_ROWS 8192
#define K_CENT 4096
#define D_DIM  256
#define LOG2E  1.4426950408889634f

#define BM 128
#define BN 128
#define NCH_TOTAL ((N_ROWS / BM) * (K_CENT / BN))   // 2048 chunks total
#define KSEG_PER_M (K_CENT / BN)                    // 32 k-segments per m-block
#define NTHREADS 256                                // 8 warps, 2x4 grid, 64x32/warp

// Row stride in smem: 512B data + 16B pad -> conflict-free ldmatrix
#define RSTRIDE 528

// ---------------- smem layout (bytes) ----------------
#define SM_WEXP  0                       // 2 x 512B (float[128] per chunk)
#define SM_RED   1024                    // 4 x 128 floats = 2048B
#define SM_X     3072                    // 128 rows x 528B = 67584
#define SM_B0    (SM_X + 128 * RSTRIDE)
#define SM_B1    (SM_B0 + 128 * RSTRIDE)
#define SMEM_TOTAL (SM_B1 + 128 * RSTRIDE)   // 205824 bytes

// ---------------- device scratch (no allocs allowed) ----------------
__device__ __align__(16) __nv_bfloat16 g_xb[N_ROWS * D_DIM];
__device__ __align__(16) __nv_bfloat16 g_cb[K_CENT * D_DIM];
__device__ __align__(16) float    g_ax[N_ROWS];       // -sigma*log2e*|x|^2
__device__ __align__(16) float    g_wexp[K_CENT];     // w * 2^(-sigma*log2e*|c|^2)
__device__ __align__(16) float    g_part[KSEG_PER_M][N_ROWS];
__device__            unsigned    g_cnt[N_ROWS / BM]; // per-m arrival counters

// ---------------- PTX helpers (sm_103-baseline only!) ----------------
static __device__ __forceinline__ uint32_t smem_u32(const void* p) {
    uint32_t a;
    asm("{ .reg .u64 t; cvta.to.shared.u64 t, %1; cvt.u32.u64 %0, t; }"
        : "=r"(a) : "l"(p));
    return a;
}

#define CPA16(dst, src) \
    asm volatile("cp.async.cg.shared.global [%0], [%1], 16;" \
                 :: "r"((uint32_t)(dst)), "l"(src) : "memory")
#define CPA_COMMIT() asm volatile("cp.async.commit_group;" ::: "memory")
#define CPA_WAIT0()  asm volatile("cp.async.wait_group 0;" ::: "memory")

#define LDMATRIX_X4(r0, r1, r2, r3, addr) \
    asm volatile("ldmatrix.sync.aligned.m8n8.x4.shared.b16 {%0,%1,%2,%3}, [%4];" \
                 : "=r"(r0), "=r"(r1), "=r"(r2), "=r"(r3) : "r"(addr))

#define MMA_BF16(d, a0, a1, a2, a3, b0, b1)                                   \
    asm volatile(                                                             \
        "mma.sync.aligned.m16n8k16.row.col.f32.bf16.bf16.f32 "                \
        "{%0,%1,%2,%3}, {%4,%5,%6,%7}, {%8,%9}, {%10,%11,%12,%13};"           \
        : "=f"((d)[0]), "=f"((d)[1]), "=f"((d)[2]), "=f"((d)[3])              \
        : "r"(a0), "r"(a1), "r"(a2), "r"(a3), "r"(b0), "r"(b1),               \
          "f"((d)[0]), "f"((d)[1]), "f"((d)[2]), "f"((d)[3]))

static __device__ __forceinline__ float ex2f(float a) {
    float p;
    asm("ex2.approx.ftz.f32 %0, %1;" : "=f"(p) : "f"(a));
    return p;
}

// ---------------- fused prep kernel ----------------
__global__ void __launch_bounds__(256)
prep_kernel(const float* __restrict__ x, const float* __restrict__ c,
            const float* __restrict__ w, const float* __restrict__ sigma) {
    int row  = blockIdx.x * 8 + (threadIdx.x >> 5);
    int lane = threadIdx.x & 31;
    const bool is_x = row < N_ROWS;
    int r = is_x ? row : row - N_ROWS;
    const float* src_f = is_x ? (x + (size_t)r * D_DIM) : (c + (size_t)r * D_DIM);
    __nv_bfloat16* dst = is_x ? (g_xb + (size_t)r * D_DIM) : (g_cb + (size_t)r * D_DIM);

    const float4* src = reinterpret_cast<const float4*>(src_f);
    float4 v0 = src[lane], v1 = src[lane + 32];
    __nv_bfloat162* o2 = reinterpret_cast<__nv_bfloat162*>(dst);
    o2[lane * 2 + 0]        = __floats2bfloat162_rn(v0.x, v0.y);
    o2[lane * 2 + 1]        = __floats2bfloat162_rn(v0.z, v0.w);
    o2[(lane + 32) * 2 + 0] = __floats2bfloat162_rn(v1.x, v1.y);
    o2[(lane + 32) * 2 + 1] = __floats2bfloat162_rn(v1.z, v1.w);
    float s = v0.x * v0.x + v0.y * v0.y + v0.z * v0.z + v0.w * v0.w
            + v1.x * v1.x + v1.y * v1.y + v1.z * v1.z + v1.w * v1.w;
#pragma unroll
    for (int o = 16; o > 0; o >>= 1) s += __shfl_xor_sync(0xffffffffu, s, o);
    if (lane == 0) {
        float a = -LOG2E * sigma[0] * s;
        if (is_x) g_ax[r] = a;
        else      g_wexp[r] = w[r] * ex2f(a);
    }
}

// one epilogue cell: array A (local mt index mtl), global row-group mtabs,
// absolute n-tile nt, wexp base wv
#define EPI_CELL(A, mtl, mtabs, nt, wv)                                       \
    do {                                                                      \
        float2 we = *reinterpret_cast<const float2*>(                         \
            (wv) + wn * 32 + (nt) * 8 + 2 * (lane & 3));                      \
        float p0 = ex2f((A)[mtl][nt][0] * S2);                                \
        float p1 = ex2f((A)[mtl][nt][1] * S2);                                \
        float p2 = ex2f((A)[mtl][nt][2] * S2);                                \
        float p3 = ex2f((A)[mtl][nt][3] * S2);                                \
        rowacc[(mtabs) * 2 + 0] = fmaf(p0, we.x, rowacc[(mtabs) * 2 + 0]);    \
        rowacc[(mtabs) * 2 + 0] = fmaf(p1, we.y, rowacc[(mtabs) * 2 + 0]);    \
        rowacc[(mtabs) * 2 + 1] = fmaf(p2, we.x, rowacc[(mtabs) * 2 + 1]);    \
        rowacc[(mtabs) * 2 + 1] = fmaf(p3, we.y, rowacc[(mtabs) * 2 + 1]);    \
    } while (0)

// ---------------- persistent main HMMA kernel ----------------
__global__ void __launch_bounds__(NTHREADS, 1)
rbf_main_kernel(const float* __restrict__ sigma, float* __restrict__ out) {
    extern __shared__ char smem[];
    const uint32_t sb = smem_u32(smem);
    const int tid  = threadIdx.x;
    const int lane = tid & 31;
    const int wid  = tid >> 5;
    const int wm   = wid >> 2;     // 0..1  (64-row slab)
    const int wn   = wid & 3;      // 0..3  (32-col slab)

    const int G  = gridDim.x;
    const int t0 = (int)(((long long)blockIdx.x * NCH_TOTAL) / G);
    const int t1 = (int)(((long long)(blockIdx.x + 1) * NCH_TOTAL) / G);
    if (t0 >= t1) return;

    const float S2 = 2.0f * LOG2E * sigma[0];

    // per-lane ldmatrix address pieces
    const int a_row = (lane & 7) + 8 * ((lane >> 3) & 1);
    const int a_kb  = (lane >> 4) * 16;
    uint32_t addrA[4];
#pragma unroll
    for (int mt = 0; mt < 4; mt++)
        addrA[mt] = sb + SM_X + (wm * 64 + mt * 16 + a_row) * RSTRIDE + a_kb;
    // B pair-load line: one x4 covers an (nt-even, nt-odd) pair for one k16
    const uint32_t bline2 =
        (uint32_t)(wn * 32 + ((lane >> 4) & 1) * 8 + (lane & 7)) * RSTRIDE
        + ((lane >> 3) & 1) * 16;

    float* red = reinterpret_cast<float*>(smem + SM_RED);
    __shared__ unsigned s_prev;

    int c = t0;
    while (c < t1) {
        const int m    = c >> 5;
        const int rend = min(t1, (m + 1) << 5);
        const int m0   = m * BM;
        const int ka   = c & 31;

        // ---- run prologue: X(m) + B(chunk c) + wexp(c) ----
        {
            const char* xg = (const char*)g_xb + (size_t)m0 * D_DIM * 2;
            const char* bg = (const char*)g_cb + (size_t)(c & 31) * BN * D_DIM * 2;
            const uint32_t bdst = sb + ((c & 1) ? SM_B1 : SM_B0);
#pragma unroll
            for (int j = 0; j < 16; j++) {
                int i = tid + j * NTHREADS;
                int row = i >> 5, c16 = i & 31;
                CPA16(sb + SM_X + row * RSTRIDE + c16 * 16, xg + (size_t)i * 16);
                CPA16(bdst     + row * RSTRIDE + c16 * 16, bg + (size_t)i * 16);
            }
            if (tid < 32)
                CPA16(sb + SM_WEXP + (c & 1) * 512 + tid * 16,
                      (const char*)(g_wexp + (size_t)(c & 31) * BN) + tid * 16);
            CPA_COMMIT();
        }

        // prefetch per-row 2^ax while the cp.async drains
        float axe[8];
#pragma unroll
        for (int r = 0; r < 8; r++)
            axe[r] = ex2f(g_ax[m0 + wm * 64 + (r >> 1) * 16 + (r & 1) * 8 + (lane >> 2)]);
        float rowacc[8];
#pragma unroll
        for (int r = 0; r < 8; r++) rowacc[r] = 0.0f;

        CPA_WAIT0();
        __syncthreads();

        // ---- chunk loop over this run's k-segments ----
        for (int cc = c; cc < rend; cc++) {
            // 1. prefetch next chunk of the run
            if (cc + 1 < rend) {
                const int ks1 = (cc + 1) & 31;
                const char* bg = (const char*)g_cb + (size_t)ks1 * BN * D_DIM * 2;
                const uint32_t bdst = sb + (((cc + 1) & 1) ? SM_B1 : SM_B0);
#pragma unroll
                for (int j = 0; j < 16; j++) {
                    int i = tid + j * NTHREADS;
                    int row = i >> 5, c16 = i & 31;
                    CPA16(bdst + row * RSTRIDE + c16 * 16, bg + (size_t)i * 16);
                }
                if (tid < 32)
                    CPA16(sb + SM_WEXP + ((cc + 1) & 1) * 512 + tid * 16,
                          (const char*)(g_wexp + (size_t)ks1 * BN) + tid * 16);
                CPA_COMMIT();
            }

            const uint32_t bbase = sb + ((cc & 1) ? SM_B1 : SM_B0) + bline2;
            const float* wv = reinterpret_cast<const float*>(
                smem + SM_WEXP + (cc & 1) * 512);

            // 2a. group 0: rows mt 0,1 x all nt (A loaded once, B pair x2)
            float acc0[2][4][4];
#pragma unroll
            for (int mt = 0; mt < 2; mt++)
#pragma unroll
                for (int nt = 0; nt < 4; nt++)
#pragma unroll
                    for (int e = 0; e < 4; e++) acc0[mt][nt][e] = 0.0f;
#pragma unroll
            for (int ks = 0; ks < 16; ks++) {
                uint32_t a[2][4];
#pragma unroll
                for (int mt = 0; mt < 2; mt++)
                    LDMATRIX_X4(a[mt][0], a[mt][1], a[mt][2], a[mt][3],
                                addrA[mt] + ks * 32);
                uint32_t e0, e1, o0, o1, e2, e3, o2, o3;
                LDMATRIX_X4(e0, e1, o0, o1, bbase + ks * 32);
                LDMATRIX_X4(e2, e3, o2, o3, bbase + 16 * RSTRIDE + ks * 32);
#pragma unroll
                for (int mt = 0; mt < 2; mt++) {
                    MMA_BF16(acc0[mt][0], a[mt][0], a[mt][1], a[mt][2], a[mt][3], e0, e1);
                    MMA_BF16(acc0[mt][1], a[mt][0], a[mt][1], a[mt][2], a[mt][3], o0, o1);
                    MMA_BF16(acc0[mt][2], a[mt][0], a[mt][1], a[mt][2], a[mt][3], e2, e3);
                    MMA_BF16(acc0[mt][3], a[mt][0], a[mt][1], a[mt][2], a[mt][3], o2, o3);
                }
            }

            // 2b. group 1: rows mt 2,3 + interleaved epilogue of group 0
            float acc1[2][4][4];
#pragma unroll
            for (int mt = 0; mt < 2; mt++)
#pragma unroll
                for (int nt = 0; nt < 4; nt++)
#pragma unroll
                    for (int e = 0; e < 4; e++) acc1[mt][nt][e] = 0.0f;
#pragma unroll
            for (int ks = 0; ks < 16; ks++) {
                uint32_t a[2][4];
#pragma unroll
                for (int mt = 0; mt < 2; mt++)
                    LDMATRIX_X4(a[mt][0], a[mt][1], a[mt][2], a[mt][3],
                                addrA[2 + mt] + ks * 32);
                uint32_t e0, e1, o0, o1, e2, e3, o2, o3;
                LDMATRIX_X4(e0, e1, o0, o1, bbase + ks * 32);
                LDMATRIX_X4(e2, e3, o2, o3, bbase + 16 * RSTRIDE + ks * 32);
#pragma unroll
                for (int mt = 0; mt < 2; mt++) {
                    MMA_BF16(acc1[mt][0], a[mt][0], a[mt][1], a[mt][2], a[mt][3], e0, e1);
                    MMA_BF16(acc1[mt][1], a[mt][0], a[mt][1], a[mt][2], a[mt][3], o0, o1);
                    MMA_BF16(acc1[mt][2], a[mt][0], a[mt][1], a[mt][2], a[mt][3], e2, e3);
                    MMA_BF16(acc1[mt][3], a[mt][0], a[mt][1], a[mt][2], a[mt][3], o2, o3);
                }
                if (ks & 1)
                    EPI_CELL(acc0, (ks >> 3), (ks >> 3), ((ks >> 1) & 3), wv);
            }
            // tail epilogue: group-1 cells (rows mt 2,3)
#pragma unroll
            for (int mt = 0; mt < 2; mt++) {
                EPI_CELL(acc1, mt, 2 + mt, 0, wv);
                EPI_CELL(acc1, mt, 2 + mt, 1, wv);
                EPI_CELL(acc1, mt, 2 + mt, 2, wv);
                EPI_CELL(acc1, mt, 2 + mt, 3, wv);
            }

            // 3. next buffer resident + all warps done with current buffers
            CPA_WAIT0();
            __syncthreads();
        }

        // ---- run flush: apply 2^ax per row, reduce, publish partial ----
#pragma unroll
        for (int r = 0; r < 8; r++) {
            rowacc[r] *= axe[r];
            rowacc[r] += __shfl_xor_sync(0xffffffffu, rowacc[r], 1);
            rowacc[r] += __shfl_xor_sync(0xffffffffu, rowacc[r], 2);
        }
        if ((lane & 3) == 0) {
#pragma unroll
            for (int r = 0; r < 8; r++) {
                int row = wm * 64 + (r >> 1) * 16 + (r & 1) * 8 + (lane >> 2);
                red[wn * 128 + row] = rowacc[r];
            }
        }
        __syncthreads();

        const int nseg = rend - c;
        if (tid < 128) {
            float s = red[tid] + red[128 + tid] + red[256 + tid] + red[384 + tid];
            g_part[ka][m0 + tid] = s;
            for (int sl = ka + 1; sl < ka + nseg; sl++)
                g_part[sl][m0 + tid] = 0.0f;
        }
        __threadfence();
        __syncthreads();
        if (tid == 0) s_prev = atomicAdd(&g_cnt[m], (unsigned)nseg);
        __syncthreads();
        if (s_prev + (unsigned)nseg == (unsigned)KSEG_PER_M) {
            __threadfence();
            if (tid < 128) {
                float o = 0.0f;
#pragma unroll
                for (int sl = 0; sl < KSEG_PER_M; sl++)
                    o += g_part[sl][m0 + tid];
                out[m0 + tid] = o;
            }
            if (tid == 0) g_cnt[m] = 0;   // restore for next graph replay
        }
        // next run's prologue syncs before any smem reuse

        c = rend;
    }
}

// ---------------- launch ----------------
extern "C" void kernel_launch(void* const* d_in, const int* in_sizes, int n_in,
                              void* d_out, int out_size) {
    const float* x  = (const float*)d_in[0];
    const float* c  = (const float*)d_in[1];
    const float* w  = (const float*)d_in[2];
    const float* sg = (const float*)d_in[3];

    int nsm = 0;
    cudaDeviceGetAttribute(&nsm, cudaDevAttrMultiProcessorCount, 0);
    if (nsm <= 0) nsm = 148;            // safe fallback
    if (nsm > NCH_TOTAL) nsm = NCH_TOTAL;

    cudaFuncSetAttribute(rbf_main_kernel,
                         cudaFuncAttributeMaxDynamicSharedMemorySize, SMEM_TOTAL);

    prep_kernel<<<(N_ROWS + K_CENT) / 8, 256>>>(x, c, w, sg);
    rbf_main_kernel<<<nsm, NTHREADS, SMEM_TOTAL>>>(sg, (float*)d_out);
}